// round 9
// baseline (speedup 1.0000x reference)
#include <cuda_runtime.h>

#define B_ 8
#define C_ 3
#define T_ 32
#define H_ 256
#define W_ 256
#define NB 8
#define HB (H_ / NB)
#define WB (W_ / NB)
#define BLOCKS_PER_FRAME (HB * WB)   // 1024
#define TPB 128
#define CTAS_PER_FRAME (BLOCKS_PER_FRAME / TPB)  // 8

// 2*cos(k*pi/16)
#define A1 1.96157056080646f
#define A2 1.84775906502257f
#define A3 1.66293922460509f
#define A4 1.41421356237310f
#define A5 1.11114046603920f
#define A6 0.76536686473018f
#define A7 0.39018064403226f

// Unnormalized DCT-II, 8 points, even/odd butterfly.
__device__ __forceinline__ void dct8(const float i0, const float i1, const float i2,
                                     const float i3, const float i4, const float i5,
                                     const float i6, const float i7, float o[8]) {
    float s0 = i0 + i7, s1 = i1 + i6, s2 = i2 + i5, s3 = i3 + i4;
    float d0 = i0 - i7, d1 = i1 - i6, d2 = i2 - i5, d3 = i3 - i4;
    o[0] = 2.0f * ((s0 + s3) + (s1 + s2));
    o[4] = A4 * ((s0 + s3) - (s1 + s2));
    o[2] = A2 * s0 + A6 * s1 - A6 * s2 - A2 * s3;
    o[6] = A6 * s0 - A2 * s1 + A2 * s2 - A6 * s3;
    o[1] = A1 * d0 + A3 * d1 + A5 * d2 + A7 * d3;
    o[3] = A3 * d0 - A7 * d1 - A1 * d2 - A5 * d3;
    o[5] = A5 * d0 - A1 * d1 + A7 * d2 + A3 * d3;
    o[7] = A7 * d0 - A5 * d1 + A3 * d2 - A1 * d3;
}

struct Row6 { float4 a0, a1, g0, g1, c0, c1; };

__device__ __forceinline__ Row6 load_row(const float* base0, const float* base1,
                                         const float* base2, int ro) {
    Row6 v;
    v.a0 = __ldcs((const float4*)(base0 + ro));
    v.a1 = __ldcs((const float4*)(base0 + ro + 4));
    v.g0 = __ldcs((const float4*)(base1 + ro));
    v.g1 = __ldcs((const float4*)(base1 + ro + 4));
    v.c0 = __ldcs((const float4*)(base2 + ro));
    v.c1 = __ldcs((const float4*)(base2 + ro + 4));
    return v;
}

__device__ __forceinline__ void gray_dct_row(const Row6& v, float o[8]) {
    const float w0 = 0.2989f, w1 = 0.587f, w2 = 0.114f;
    float p0 = w0 * v.a0.x + w1 * v.g0.x + w2 * v.c0.x;
    float p1 = w0 * v.a0.y + w1 * v.g0.y + w2 * v.c0.y;
    float p2 = w0 * v.a0.z + w1 * v.g0.z + w2 * v.c0.z;
    float p3 = w0 * v.a0.w + w1 * v.g0.w + w2 * v.c0.w;
    float p4 = w0 * v.a1.x + w1 * v.g1.x + w2 * v.c1.x;
    float p5 = w0 * v.a1.y + w1 * v.g1.y + w2 * v.c1.y;
    float p6 = w0 * v.a1.z + w1 * v.g1.z + w2 * v.c1.z;
    float p7 = w0 * v.a1.w + w1 * v.g1.w + w2 * v.c1.w;
    dct8(p0, p1, p2, p3, p4, p5, p6, p7, o);
}

__global__ __launch_bounds__(TPB)
void dct8x8_kernel(const float* __restrict__ x, float* __restrict__ out) {
    // 16B granules; XOR swizzle keeps STS.128 and LDS.128 conflict-free.
    __shared__ float4 stage[TPB * 16];   // 32 KB

    const int tid  = threadIdx.x;
    const int lane = tid & 31;
    const int warp = tid >> 5;
    const int cta_in_frame = blockIdx.x & (CTAS_PER_FRAME - 1);
    const int frame = blockIdx.x / CTAS_PER_FRAME;    // b*T + t
    const int b = frame >> 5;
    const int t = frame & 31;

    const int p  = cta_in_frame * TPB + tid;          // block index in frame
    const int hb = p >> 5;
    const int wb = p & 31;

    const long long chan_stride = (long long)T_ * H_ * W_;
    const float* base0 = x
        + (long long)b * C_ * chan_stride
        + (long long)t * H_ * W_
        + (long long)(hb * NB) * W_
        + (long long)(wb * NB);
    const float* base1 = base0 + chan_stride;
    const float* base2 = base1 + chan_stride;

    // Software pipeline, prefetch distance 2: rows r+1, r+2 in flight
    // while row r's gray+DCT math runs.
    float Y[8][8];
    Row6 buf0 = load_row(base0, base1, base2, 0);
    Row6 buf1 = load_row(base0, base1, base2, W_);
    #pragma unroll
    for (int r = 0; r < 8; ++r) {
        Row6 nxt;
        if (r < 6) nxt = load_row(base0, base1, base2, (r + 2) * W_);
        gray_dct_row(buf0, Y[r]);
        buf0 = buf1;
        if (r < 6) buf1 = nxt;
    }

    // Stage 2: column DCT
    float Z[8][8];
    #pragma unroll
    for (int l = 0; l < 8; ++l) {
        float col[8];
        dct8(Y[0][l], Y[1][l], Y[2][l], Y[3][l],
             Y[4][l], Y[5][l], Y[6][l], Y[7][l], col);
        #pragma unroll
        for (int k = 0; k < 8; ++k) Z[k][l] = col[k];
    }

    // Stage results into smem (swizzled), 16 granules of 16B per thread.
    const float4* zsrc = (const float4*)&Z[0][0];
    #pragma unroll
    for (int i = 0; i < 16; ++i) {
        stage[tid * 16 + (i ^ (tid & 15))] = zsrc[i];
    }
    __syncwarp();

    // Coalesced store: each warp writes its own 32 threads' 8KB contiguously.
    float4* out4 = (float4*)out
        + (long long)frame * (BLOCKS_PER_FRAME * 16)
        + (long long)cta_in_frame * (TPB * 16);
    #pragma unroll
    for (int c = 0; c < 16; ++c) {
        int m  = warp * 512 + c * 32 + lane;   // linear granule within CTA
        int tp = m >> 4;
        int j  = m & 15;
        float4 v = stage[tp * 16 + (j ^ (tp & 15))];
        __stcs(&out4[m], v);
    }
}

extern "C" void kernel_launch(void* const* d_in, const int* in_sizes, int n_in,
                              void* d_out, int out_size) {
    const float* x = (const float*)d_in[0];
    float* out = (float*)d_out;
    const int grid = B_ * T_ * CTAS_PER_FRAME;  // 2048
    dct8x8_kernel<<<grid, TPB>>>(x, out);
}

// round 10
// speedup vs baseline: 1.0147x; 1.0147x over previous
#include <cuda_runtime.h>

#define B_ 8
#define C_ 3
#define T_ 32
#define H_ 256
#define W_ 256
#define NB 8
#define HB (H_ / NB)
#define WB (W_ / NB)
#define BLOCKS_PER_FRAME (HB * WB)   // 1024
#define TPB 64
#define CTAS_PER_FRAME (BLOCKS_PER_FRAME / TPB)  // 16

// 2*cos(k*pi/16)
#define A1 1.96157056080646f
#define A2 1.84775906502257f
#define A3 1.66293922460509f
#define A4 1.41421356237310f
#define A5 1.11114046603920f
#define A6 0.76536686473018f
#define A7 0.39018064403226f

// Unnormalized DCT-II, 8 points, even/odd butterfly.
__device__ __forceinline__ void dct8(const float i0, const float i1, const float i2,
                                     const float i3, const float i4, const float i5,
                                     const float i6, const float i7, float o[8]) {
    float s0 = i0 + i7, s1 = i1 + i6, s2 = i2 + i5, s3 = i3 + i4;
    float d0 = i0 - i7, d1 = i1 - i6, d2 = i2 - i5, d3 = i3 - i4;
    o[0] = 2.0f * ((s0 + s3) + (s1 + s2));
    o[4] = A4 * ((s0 + s3) - (s1 + s2));
    o[2] = A2 * s0 + A6 * s1 - A6 * s2 - A2 * s3;
    o[6] = A6 * s0 - A2 * s1 + A2 * s2 - A6 * s3;
    o[1] = A1 * d0 + A3 * d1 + A5 * d2 + A7 * d3;
    o[3] = A3 * d0 - A7 * d1 - A1 * d2 - A5 * d3;
    o[5] = A5 * d0 - A1 * d1 + A7 * d2 + A3 * d3;
    o[7] = A7 * d0 - A5 * d1 + A3 * d2 - A1 * d3;
}

struct Row6 { float4 a0, a1, g0, g1, c0, c1; };

__device__ __forceinline__ Row6 load_row(const float* base0, const float* base1,
                                         const float* base2, int ro) {
    Row6 v;
    v.a0 = __ldcs((const float4*)(base0 + ro));
    v.a1 = __ldcs((const float4*)(base0 + ro + 4));
    v.g0 = __ldcs((const float4*)(base1 + ro));
    v.g1 = __ldcs((const float4*)(base1 + ro + 4));
    v.c0 = __ldcs((const float4*)(base2 + ro));
    v.c1 = __ldcs((const float4*)(base2 + ro + 4));
    return v;
}

__device__ __forceinline__ void gray_dct_row(const Row6& v, float o[8]) {
    const float w0 = 0.2989f, w1 = 0.587f, w2 = 0.114f;
    float p0 = w0 * v.a0.x + w1 * v.g0.x + w2 * v.c0.x;
    float p1 = w0 * v.a0.y + w1 * v.g0.y + w2 * v.c0.y;
    float p2 = w0 * v.a0.z + w1 * v.g0.z + w2 * v.c0.z;
    float p3 = w0 * v.a0.w + w1 * v.g0.w + w2 * v.c0.w;
    float p4 = w0 * v.a1.x + w1 * v.g1.x + w2 * v.c1.x;
    float p5 = w0 * v.a1.y + w1 * v.g1.y + w2 * v.c1.y;
    float p6 = w0 * v.a1.z + w1 * v.g1.z + w2 * v.c1.z;
    float p7 = w0 * v.a1.w + w1 * v.g1.w + w2 * v.c1.w;
    dct8(p0, p1, p2, p3, p4, p5, p6, p7, o);
}

__global__ __launch_bounds__(TPB)
void dct8x8_kernel(const float* __restrict__ x, float* __restrict__ out) {
    // 16B granules; XOR swizzle keeps STS.128 and LDS.128 conflict-free.
    __shared__ float4 stage[TPB * 16];   // 16 KB

    const int tid  = threadIdx.x;
    const int lane = tid & 31;
    const int warp = tid >> 5;
    const int cta_in_frame = blockIdx.x & (CTAS_PER_FRAME - 1);
    const int frame = blockIdx.x / CTAS_PER_FRAME;    // b*T + t
    const int b = frame >> 5;
    const int t = frame & 31;

    const int p  = cta_in_frame * TPB + tid;          // block index in frame
    const int hb = p >> 5;
    const int wb = p & 31;

    const long long chan_stride = (long long)T_ * H_ * W_;
    const float* base0 = x
        + (long long)b * C_ * chan_stride
        + (long long)t * H_ * W_
        + (long long)(hb * NB) * W_
        + (long long)(wb * NB);
    const float* base1 = base0 + chan_stride;
    const float* base2 = base1 + chan_stride;

    // Software pipeline, prefetch distance 2.
    float Y[8][8];
    Row6 buf0 = load_row(base0, base1, base2, 0);
    Row6 buf1 = load_row(base0, base1, base2, W_);
    #pragma unroll
    for (int r = 0; r < 8; ++r) {
        Row6 nxt;
        if (r < 6) nxt = load_row(base0, base1, base2, (r + 2) * W_);
        gray_dct_row(buf0, Y[r]);
        buf0 = buf1;
        if (r < 6) buf1 = nxt;
    }

    // Stage 2: column DCT
    float Z[8][8];
    #pragma unroll
    for (int l = 0; l < 8; ++l) {
        float col[8];
        dct8(Y[0][l], Y[1][l], Y[2][l], Y[3][l],
             Y[4][l], Y[5][l], Y[6][l], Y[7][l], col);
        #pragma unroll
        for (int k = 0; k < 8; ++k) Z[k][l] = col[k];
    }

    // Stage results into smem (swizzled), 16 granules of 16B per thread.
    const float4* zsrc = (const float4*)&Z[0][0];
    #pragma unroll
    for (int i = 0; i < 16; ++i) {
        stage[tid * 16 + (i ^ (tid & 15))] = zsrc[i];
    }
    __syncwarp();

    // Coalesced store: each warp writes its own 32 threads' 8KB contiguously.
    float4* out4 = (float4*)out
        + (long long)frame * (BLOCKS_PER_FRAME * 16)
        + (long long)cta_in_frame * (TPB * 16);
    #pragma unroll
    for (int c = 0; c < 16; ++c) {
        int m  = warp * 512 + c * 32 + lane;   // linear granule within CTA
        int tp = m >> 4;
        int j  = m & 15;
        float4 v = stage[tp * 16 + (j ^ (tp & 15))];
        __stcs(&out4[m], v);
    }
}

extern "C" void kernel_launch(void* const* d_in, const int* in_sizes, int n_in,
                              void* d_out, int out_size) {
    const float* x = (const float*)d_in[0];
    float* out = (float*)d_out;
    const int grid = B_ * T_ * CTAS_PER_FRAME;  // 4096
    dct8x8_kernel<<<grid, TPB>>>(x, out);
}